// round 17
// baseline (speedup 1.0000x reference)
#include <cuda_runtime.h>
#include <cuda_fp16.h>
#include <cuda_bf16.h>
#include <math.h>

#define N_NODES 100000
#define E_EDGES 3200000
#define TOT_E   (E_EDGES + N_NODES)   // edges + self loops = 3,300,000
#define IN_DIM  512
#define HID     256
#define NC      40
#define NC2     (NC / 2)              // 20 half2 words per row
#define NQ      5                     // 5 float4 chunks per row (80 B)
#define SCAN_B  1024
#define NBLK    ((N_NODES + SCAN_B - 1) / SCAN_B)   // 98
#define PLP_BLOCKS 444                // 3 CTAs/SM on 148 SMs: all co-resident

// ---------------- scratch (device globals; no allocations allowed) ----------
__device__ int     g_degcnt[N_NODES];
__device__ int     g_colcnt[N_NODES];
__device__ int     g_colptr[N_NODES + 1];
__device__ int     g_cur[N_NODES];
__device__ float   g_dis[N_NODES];
__device__ int2    g_edge[TOT_E];     // (row, norm-as-int-bits)
__device__ __align__(16) __half2 g_B0h[(size_t)N_NODES * NC2];
__device__ __align__(16) __half2 g_B1h[(size_t)N_NODES * NC2];
__device__ float   g_h[(size_t)N_NODES * HID];
__device__ __align__(16) float g_logits[(size_t)N_NODES * NC];
__device__ __nv_bfloat16 g_w1hi[(size_t)HID * IN_DIM];
__device__ __nv_bfloat16 g_w1lo[(size_t)HID * IN_DIM];
__device__ int     g_bsum[NBLK + 2];
__device__ int     g_unm[N_NODES];   // compacted unmasked node ids
__device__ int     g_nun;            // count of unmasked nodes
__device__ unsigned g_bar;           // persistent-PLP grid barrier counter
__device__ int     g_ei64;    // 1 if edge_index stored as int64, 0 if int32
__device__ int     g_mask32;  // 1 if train_mask stored as int32, 0 if bool/byte

// ---------------- dtype detection (deterministic, graph-capturable) ---------
__global__ void k_detect(const int* __restrict__ ei32,
                         const unsigned char* __restrict__ mask) {
    __shared__ int s_ei_nz, s_mask_nz;
    int t = threadIdx.x;
    if (t == 0) { s_ei_nz = 0; s_mask_nz = 0; g_nun = 0; g_bar = 0; }
    __syncthreads();
    int eidx = (t * 12347 + 5) % E_EDGES;          // sample odd word of pair
    if (ei32[2 * eidx + 1] != 0) atomicOr(&s_ei_nz, 1);
    int midx = (t * 97 + 1) % (N_NODES / 4);
    if (mask[4 * midx + 1] != 0) atomicOr(&s_mask_nz, 1);
    __syncthreads();
    if (t == 0) {
        g_ei64 = (s_ei_nz == 0) ? 1 : 0;
        g_mask32 = (s_mask_nz == 0) ? 1 : 0;
    }
}

__device__ __forceinline__ void load_edge(const void* ei, int i, int& r, int& c) {
    if (g_ei64) {
        const long long* p = (const long long*)ei;
        r = (int)p[i];
        c = (int)p[(size_t)E_EDGES + i];
    } else {
        const int* p = (const int*)ei;
        r = p[i];
        c = p[(size_t)E_EDGES + i];
    }
}

__device__ __forceinline__ bool load_mask(const void* mask, int v) {
    if (g_mask32) return ((const int*)mask)[v] != 0;
    return ((const unsigned char*)mask)[v] != 0;
}

// ---------------- mma / cp.async helpers (sm_103a) ----------------------------
__device__ __forceinline__ void ldsm4(unsigned& r0, unsigned& r1,
                                      unsigned& r2, unsigned& r3, unsigned a) {
    asm volatile("ldmatrix.sync.aligned.m8n8.x4.shared.b16 {%0,%1,%2,%3}, [%4];"
                 : "=r"(r0), "=r"(r1), "=r"(r2), "=r"(r3) : "r"(a));
}
__device__ __forceinline__ void mma16816(float* c, const unsigned* a,
                                         const unsigned* b) {
    asm("mma.sync.aligned.m16n8k16.row.col.f32.bf16.bf16.f32 "
        "{%0,%1,%2,%3}, {%4,%5,%6,%7}, {%8,%9}, {%0,%1,%2,%3};"
        : "+f"(c[0]), "+f"(c[1]), "+f"(c[2]), "+f"(c[3])
        : "r"(a[0]), "r"(a[1]), "r"(a[2]), "r"(a[3]), "r"(b[0]), "r"(b[1]));
}
__device__ __forceinline__ void cpasync16(unsigned smem, const void* g) {
    asm volatile("cp.async.cg.shared.global [%0], [%1], 16;"
                 :: "r"(smem), "l"(g));
}
__device__ __forceinline__ void cpasync_commit() {
    asm volatile("cp.async.commit_group;");
}
__device__ __forceinline__ void cpasync_wait0() {
    asm volatile("cp.async.wait_group 0;");
}

// grid barrier: monotonic counter (reset per launch in k_detect).
__device__ __forceinline__ void gridbar(unsigned target) {
    __threadfence();                 // publish this thread's stores
    __syncthreads();
    if (threadIdx.x == 0) {
        atomicAdd(&g_bar, 1u);
        volatile unsigned* p = &g_bar;
        while (*p < target) { }
    }
    __syncthreads();
}

// ---------------- setup kernels ---------------------------------------------
__global__ void k_init(const void* __restrict__ mask) {
    int i = blockIdx.x * blockDim.x + threadIdx.x;
    if (i < N_NODES) {
        g_degcnt[i] = 1;                              // self loop counts in deg
        bool m = load_mask(mask, i);
        g_colcnt[i] = m ? 0 : 1;                      // CSC drops masked dst
        if (!m) {
            int p = atomicAdd(&g_nun, 1);
            g_unm[p] = i;                             // compacted list
        }
    }
}

// split W1 into bf16 hi/lo (once per launch; 131072 elements)
__global__ void k_wsplit(const float* __restrict__ w1) {
    int i = blockIdx.x * blockDim.x + threadIdx.x;
    if (i < HID * IN_DIM) {
        float w = w1[i];
        __nv_bfloat16 hi = __float2bfloat16(w);
        g_w1hi[i] = hi;
        g_w1lo[i] = __float2bfloat16(w - __bfloat162float(hi));
    }
}

// fused: B0h = fp16(label_init) for ALL rows; B1h masked rows = fp16(hard)
__global__ void k_convstamp(const float* __restrict__ linit,
                            const void* __restrict__ mask,
                            const float* __restrict__ hard) {
    int i = blockIdx.x * blockDim.x + threadIdx.x;   // node*NC2 + word
    if (i >= N_NODES * NC2) return;
    float2 v = ((const float2*)linit)[i];
    g_B0h[i] = __float22half2_rn(v);
    int nd = i / NC2;
    if (load_mask(mask, nd)) {
        float2 hv = ((const float2*)hard)[i];
        g_B1h[i] = __float22half2_rn(hv);
    }
}

__global__ void k_hist(const void* __restrict__ ei, const void* __restrict__ mask) {
    int i = blockIdx.x * blockDim.x + threadIdx.x;
    if (i < E_EDGES) {
        int r, c;
        load_edge(ei, i, r, c);
        atomicAdd(&g_degcnt[r], 1);
        if (!load_mask(mask, c)) atomicAdd(&g_colcnt[c], 1);
    }
}

__global__ void k_dis() {
    int i = blockIdx.x * blockDim.x + threadIdx.x;
    if (i < N_NODES) g_dis[i] = rsqrtf((float)g_degcnt[i]);
}

// exclusive scan of g_colcnt -> g_colptr (3 stages)
__global__ void k_scan1() {
    __shared__ int s[SCAN_B];
    int t = threadIdx.x;
    int gid = blockIdx.x * SCAN_B + t;
    int v = (gid < N_NODES) ? g_colcnt[gid] : 0;
    s[t] = v;
    __syncthreads();
    for (int off = 1; off < SCAN_B; off <<= 1) {
        int tmp = (t >= off) ? s[t - off] : 0;
        __syncthreads();
        s[t] += tmp;
        __syncthreads();
    }
    if (gid < N_NODES) g_colptr[gid] = s[t] - v;      // exclusive within block
    if (t == SCAN_B - 1) g_bsum[blockIdx.x] = s[t];   // block total
}

__global__ void k_scan2() {  // 128 threads, NBLK=98 <= 128
    __shared__ int s[128];
    int t = threadIdx.x;
    int v = (t < NBLK) ? g_bsum[t] : 0;
    s[t] = v;
    __syncthreads();
    for (int off = 1; off < 128; off <<= 1) {
        int tmp = (t >= off) ? s[t - off] : 0;
        __syncthreads();
        s[t] += tmp;
        __syncthreads();
    }
    if (t < NBLK) g_bsum[t] = s[t] - v;               // exclusive
    if (t == NBLK - 1) g_bsum[NBLK] = s[t];           // grand total
}

__global__ void k_scan3() {
    int gid = blockIdx.x * SCAN_B + threadIdx.x;
    if (gid < N_NODES) {
        int v = g_colptr[gid] + g_bsum[blockIdx.x];
        g_colptr[gid] = v;
        g_cur[gid] = v;
    }
    if (blockIdx.x == 0 && threadIdx.x == 0) g_colptr[N_NODES] = g_bsum[NBLK];
}

__global__ void k_fill(const void* __restrict__ ei, const void* __restrict__ mask) {
    int i = blockIdx.x * blockDim.x + threadIdx.x;
    if (i >= TOT_E) return;
    int r, c;
    if (i < E_EDGES) {
        load_edge(ei, i, r, c);
    } else {
        r = c = i - E_EDGES;   // self loop
    }
    if (load_mask(mask, c)) return;   // masked destinations are never read
    float nm = g_dis[r] * g_dis[c];
    int pos = atomicAdd(&g_cur[c], 1);
    g_edge[pos] = make_int2(r, __float_as_int(nm));   // one 8B store
}

// ---------------- GEMM1 (tensor cores, pipelined) -----------------------------
#define GBM 128
#define GBK 32
#define SA_HI   0
#define SA_LO   8192
#define SB_HI0  16384
#define SB_HI1  32768
#define SB_LO0  49152
#define SB_LO1  65536
#define GSMEM   81920

__device__ __forceinline__ unsigned sw_off(int row, int col) {
    int chunk = (col >> 3) ^ ((row >> 1) & 3);
    return (unsigned)(row * 64 + chunk * 16 + (col & 7) * 2);
}

__global__ __launch_bounds__(512)
void k_gemm1t(const float* __restrict__ X, const float* __restrict__ b1) {
    extern __shared__ __align__(16) char dyn[];
    unsigned uBase = (unsigned)__cvta_generic_to_shared(dyn);
    int tid = threadIdx.x;
    int lane = tid & 31, warp = tid >> 5;
    int wm = warp & 3;
    int wn = warp >> 2;
    int mB = blockIdx.x * GBM;

    int aRow[2], aQ[2];
#pragma unroll
    for (int i = 0; i < 2; ++i) {
        int slot = tid + 512 * i;
        aRow[i] = slot >> 3; aQ[i] = slot & 7;
    }
    int bMat[4], bRow[4], bQ[4];
#pragma unroll
    for (int i = 0; i < 4; ++i) {
        int slot = tid + 512 * i;
        bMat[i] = slot >> 10;
        int s = slot & 1023;
        bRow[i] = s >> 2; bQ[i] = s & 3;
    }

    float c[2][8][4];
#pragma unroll
    for (int i = 0; i < 2; i++)
#pragma unroll
        for (int j = 0; j < 8; j++)
#pragma unroll
            for (int k = 0; k < 4; k++) c[i][j][k] = 0.f;

    auto issueB = [&](int kt, int buf) {
#pragma unroll
        for (int i = 0; i < 4; ++i) {
            const __nv_bfloat16* src = (bMat[i] ? g_w1lo : g_w1hi)
                                       + (size_t)bRow[i] * IN_DIM + kt + bQ[i] * 8;
            unsigned base = bMat[i] ? (buf ? SB_LO1 : SB_LO0)
                                    : (buf ? SB_HI1 : SB_HI0);
            unsigned off = (unsigned)(bRow[i] * 64 +
                             ((bQ[i] ^ ((bRow[i] >> 1) & 3)) * 16));
            cpasync16(uBase + base + off, src);
        }
        cpasync_commit();
    };
    float4 pa[2];
    auto loadA = [&](int kt) {
#pragma unroll
        for (int i = 0; i < 2; ++i) {
            int gm = mB + aRow[i];
            pa[i] = (gm < N_NODES)
                ? *(const float4*)(X + (size_t)gm * IN_DIM + kt + aQ[i] * 4)
                : make_float4(0.f, 0.f, 0.f, 0.f);
        }
    };
    auto storeA = [&]() {
#pragma unroll
        for (int i = 0; i < 2; ++i) {
            float vf[4] = {pa[i].x, pa[i].y, pa[i].z, pa[i].w};
            unsigned hw[2], lw[2];
#pragma unroll
            for (int p = 0; p < 2; p++) {
                __nv_bfloat16 h0 = __float2bfloat16(vf[2 * p]);
                __nv_bfloat16 h1 = __float2bfloat16(vf[2 * p + 1]);
                __nv_bfloat16 l0 = __float2bfloat16(vf[2 * p] - __bfloat162float(h0));
                __nv_bfloat16 l1 = __float2bfloat16(vf[2 * p + 1] - __bfloat162float(h1));
                __nv_bfloat162 hp = __nv_bfloat162(h0, h1);
                __nv_bfloat162 lp = __nv_bfloat162(l0, l1);
                hw[p] = *reinterpret_cast<unsigned*>(&hp);
                lw[p] = *reinterpret_cast<unsigned*>(&lp);
            }
            unsigned off = sw_off(aRow[i], aQ[i] * 4);
            *(uint2*)(dyn + SA_HI + off) = make_uint2(hw[0], hw[1]);
            *(uint2*)(dyn + SA_LO + off) = make_uint2(lw[0], lw[1]);
        }
    };

    loadA(0);
    issueB(0, 0);

    int it = 0;
    for (int kt = 0; kt < IN_DIM; kt += GBK, it ^= 1) {
        storeA();
        cpasync_wait0();
        __syncthreads();

        int kn = kt + GBK;
        if (kn < IN_DIM) {
            issueB(kn, it ^ 1);
            loadA(kn);
        }

        unsigned uBh = uBase + (it ? SB_HI1 : SB_HI0);
        unsigned uBl = uBase + (it ? SB_LO1 : SB_LO0);
#pragma unroll
        for (int ks = 0; ks < GBK; ks += 16) {
            unsigned ahi[2][4], alo[2][4];
#pragma unroll
            for (int mt = 0; mt < 2; mt++) {
                int r = wm * 32 + mt * 16 + (lane & 15);
                int col = ks + ((lane & 16) ? 8 : 0);
                unsigned off = sw_off(r, col);
                ldsm4(ahi[mt][0], ahi[mt][1], ahi[mt][2], ahi[mt][3],
                      uBase + SA_HI + off);
                ldsm4(alo[mt][0], alo[mt][1], alo[mt][2], alo[mt][3],
                      uBase + SA_LO + off);
            }
#pragma unroll
            for (int np = 0; np < 4; np++) {
                int n = wn * 64 + np * 16 + (lane & 7) + ((lane & 16) ? 8 : 0);
                int col = ks + ((lane & 8) ? 8 : 0);
                unsigned off = sw_off(n, col);
                unsigned bh[4], bl[4];
                ldsm4(bh[0], bh[1], bh[2], bh[3], uBh + off);
                ldsm4(bl[0], bl[1], bl[2], bl[3], uBl + off);
                mma16816(c[0][2 * np],     ahi[0], bh);
                mma16816(c[1][2 * np],     ahi[1], bh);
                mma16816(c[0][2 * np + 1], ahi[0], bh + 2);
                mma16816(c[1][2 * np + 1], ahi[1], bh + 2);
                mma16816(c[0][2 * np],     ahi[0], bl);
                mma16816(c[1][2 * np],     ahi[1], bl);
                mma16816(c[0][2 * np + 1], ahi[0], bl + 2);
                mma16816(c[1][2 * np + 1], ahi[1], bl + 2);
                mma16816(c[0][2 * np],     alo[0], bh);
                mma16816(c[1][2 * np],     alo[1], bh);
                mma16816(c[0][2 * np + 1], alo[0], bh + 2);
                mma16816(c[1][2 * np + 1], alo[1], bh + 2);
            }
        }
        __syncthreads();
    }

    int g = lane >> 2, t = lane & 3;
#pragma unroll
    for (int mt = 0; mt < 2; mt++) {
        int gm0 = mB + wm * 32 + mt * 16 + g;
#pragma unroll
        for (int j = 0; j < 8; j++) {
            int n = wn * 64 + j * 8 + t * 2;
            float bb0 = __ldg(b1 + n), bb1 = __ldg(b1 + n + 1);
            if (gm0 < N_NODES) {
                float2 o = make_float2(fmaxf(c[mt][j][0] + bb0, 0.f),
                                       fmaxf(c[mt][j][1] + bb1, 0.f));
                *(float2*)(g_h + (size_t)gm0 * HID + n) = o;
            }
            int gm1 = gm0 + 8;
            if (gm1 < N_NODES) {
                float2 o = make_float2(fmaxf(c[mt][j][2] + bb0, 0.f),
                                       fmaxf(c[mt][j][3] + bb1, 0.f));
                *(float2*)(g_h + (size_t)gm1 * HID + n) = o;
            }
        }
    }
}

// ---------------- PLP: ALL 10 steps in one persistent kernel -----------------
// Grid = PLP_BLOCKS (co-resident); grid barrier between steps. Buffer gathers
// use __ldcg (L2-coherent) since L1 is NOT flushed inside one kernel.
__global__ __launch_bounds__(256)
void k_plp10(const void* __restrict__ mask, const float* __restrict__ hard) {
    int tid = blockIdx.x * blockDim.x + threadIdx.x;
    int gwarp = tid >> 5;
    int lane = tid & 31;
    int nwarps = (gridDim.x * blockDim.x) >> 5;
    int nthreads = gridDim.x * blockDim.x;
    int nun = g_nun;

    int g = lane / 5;                   // 0..5 (lanes 30,31 -> 6)
    int q = lane - g * 5;               // 0..4
    bool lane_ok = lane < 30;

    for (int step = 1; step <= 10; ++step) {
        const float4* src4 = (const float4*)((step & 1) ? g_B0h : g_B1h);
        uint4* dst4 = (uint4*)((step & 1) ? g_B1h : g_B0h);

        for (int widx = gwarp; widx < nun; widx += nwarps) {
            int v = g_unm[widx];
            int e = g_colptr[v];
            const int end = g_colptr[v + 1];

            float2 acc0 = {0.f, 0.f}, acc1 = {0.f, 0.f};
            float2 acc2 = {0.f, 0.f}, acc3 = {0.f, 0.f};

            int2 en = (lane_ok && e + g < end) ? g_edge[e + g] : make_int2(0, 0);
            while (e < end) {
                int e2 = e + 6;
                int2 en_next = (lane_ok && e2 + g < end) ? g_edge[e2 + g]
                                                         : make_int2(0, 0);
                float nrm = __int_as_float(en.y);
                float4 raw = __ldcg(src4 + (size_t)en.x * NQ + q);
                const __half2* hp = (const __half2*)&raw;
                float2 f0 = __half22float2(hp[0]);
                float2 f1 = __half22float2(hp[1]);
                float2 f2 = __half22float2(hp[2]);
                float2 f3 = __half22float2(hp[3]);
                acc0.x += nrm * f0.x; acc0.y += nrm * f0.y;
                acc1.x += nrm * f1.x; acc1.y += nrm * f1.y;
                acc2.x += nrm * f2.x; acc2.y += nrm * f2.y;
                acc3.x += nrm * f3.x; acc3.y += nrm * f3.y;
                en = en_next;
                e = e2;
            }

            float vals[8] = {acc0.x, acc0.y, acc1.x, acc1.y,
                             acc2.x, acc2.y, acc3.x, acc3.y};
            float orig[8];
#pragma unroll
            for (int t = 0; t < 8; t++) orig[t] = vals[t];
#pragma unroll
            for (int k = 1; k < 6; k++) {
                int srcl = lane + 5 * k;
#pragma unroll
                for (int t = 0; t < 8; t++)
                    vals[t] += __shfl_sync(0xffffffffu, orig[t], srcl & 31);
            }

            if (lane < NQ) {
                __half2 h0 = __floats2half2_rn(vals[0], vals[1]);
                __half2 h1 = __floats2half2_rn(vals[2], vals[3]);
                __half2 h2 = __floats2half2_rn(vals[4], vals[5]);
                __half2 h3 = __floats2half2_rn(vals[6], vals[7]);
                uint4 u;
                u.x = *reinterpret_cast<unsigned*>(&h0);
                u.y = *reinterpret_cast<unsigned*>(&h1);
                u.z = *reinterpret_cast<unsigned*>(&h2);
                u.w = *reinterpret_cast<unsigned*>(&h3);
                dst4[(size_t)v * NQ + lane] = u;
            }
        }

        if (step == 2) {
            // stamp masked B0h rows = hard (disjoint from step-2's unmasked
            // B0h writes; needed before step 3 reads B0h)
            for (int i = tid; i < N_NODES * NC2; i += nthreads) {
                if (load_mask(mask, i / NC2)) {
                    float2 hv = ((const float2*)hard)[i];
                    g_B0h[i] = __float22half2_rn(hv);
                }
            }
        }

        gridbar((unsigned)(gridDim.x * step));
    }
}

// ---------------- FC2 GEMM (no combine): g_logits = g_h @ W2^T + b2 ----------
__global__ __launch_bounds__(256, 2)
void k_fc2(const float* __restrict__ W2, const float* __restrict__ b2) {
    __shared__ __align__(16) float sH[32][256];   // 32 KB
    __shared__ float sW[32][48];                  // 6 KB (40 used, padded)
    int tid = threadIdx.x;
    int m0 = blockIdx.x * 256;
    int tn = tid & 31, tc = tid >> 5;

    float acc[8][5];
#pragma unroll
    for (int i = 0; i < 8; i++)
#pragma unroll
        for (int j = 0; j < 5; j++) acc[i][j] = 0.f;

    for (int k0 = 0; k0 < HID; k0 += 32) {
#pragma unroll
        for (int i = 0; i < 8; ++i) {
            int slot = tid + 256 * i;
            int node = slot >> 3;
            int kk = (slot & 7) << 2;
            int gm = m0 + node;
            float4 v = make_float4(0.f, 0.f, 0.f, 0.f);
            if (gm < N_NODES)
                v = *(const float4*)(g_h + (size_t)gm * HID + k0 + kk);
            sH[kk + 0][node] = v.x; sH[kk + 1][node] = v.y;
            sH[kk + 2][node] = v.z; sH[kk + 3][node] = v.w;
        }
#pragma unroll
        for (int i = 0; i < 2; ++i) {
            int slot = tid + 256 * i;
            if (slot < 320) {
                int c = slot >> 3;
                int kk = (slot & 7) << 2;
                float4 v = *(const float4*)(W2 + (size_t)c * HID + k0 + kk);
                sW[kk + 0][c] = v.x; sW[kk + 1][c] = v.y;
                sW[kk + 2][c] = v.z; sW[kk + 3][c] = v.w;
            }
        }
        __syncthreads();
#pragma unroll
        for (int kk = 0; kk < 32; ++kk) {
            float4 a0 = *(const float4*)&sH[kk][tn * 8];
            float4 a1 = *(const float4*)&sH[kk][tn * 8 + 4];
            float wr[5];
#pragma unroll
            for (int j = 0; j < 5; j++) wr[j] = sW[kk][tc * 5 + j];
            float ar[8] = {a0.x, a0.y, a0.z, a0.w, a1.x, a1.y, a1.z, a1.w};
#pragma unroll
            for (int i = 0; i < 8; i++)
#pragma unroll
                for (int j = 0; j < 5; j++) acc[i][j] += ar[i] * wr[j];
        }
        __syncthreads();
    }

#pragma unroll
    for (int i = 0; i < 8; i++) {
        int node = m0 + tn * 8 + i;
        if (node >= N_NODES) continue;
#pragma unroll
        for (int j = 0; j < 5; j++) {
            int c = tc * 5 + j;
            g_logits[(size_t)node * NC + c] = acc[i][j] + b2[c];
        }
    }
}

// ---------------- final combine (streaming, cheap) ----------------------------
__global__ __launch_bounds__(256)
void k_combine(const float* __restrict__ alpha, float* __restrict__ out) {
    int i = blockIdx.x * blockDim.x + threadIdx.x;   // float4 index
    if (i >= N_NODES * (NC / 4)) return;
    int node = i / (NC / 4);
    int q = i - node * (NC / 4);                     // 0..9
    float aa = 1.f / (1.f + expf(-__ldg(alpha + node)));
    float na = 1.f - aa;
    float4 lg = ((const float4*)g_logits)[i];
    __half2 p0 = g_B0h[(size_t)node * NC2 + 2 * q];
    __half2 p1 = g_B0h[(size_t)node * NC2 + 2 * q + 1];
    float2 f0 = __half22float2(p0), f1 = __half22float2(p1);
    float4 o;
    o.x = aa * f0.x + na * lg.x;
    o.y = aa * f0.y + na * lg.y;
    o.z = aa * f1.x + na * lg.z;
    o.w = aa * f1.y + na * lg.w;
    ((float4*)out)[i] = o;
}

// ---------------- launch ------------------------------------------------------
extern "C" void kernel_launch(void* const* d_in, const int* in_sizes, int n_in,
                              void* d_out, int out_size) {
    const float* x     = (const float*)d_in[0];
    const void*  ei    = d_in[1];
    const float* linit = (const float*)d_in[2];
    const void*  mask  = d_in[3];
    const float* hard  = (const float*)d_in[4];
    const float* w1    = (const float*)d_in[5];
    const float* b1    = (const float*)d_in[6];
    const float* w2    = (const float*)d_in[7];
    const float* b2    = (const float*)d_in[8];
    const float* alpha = (const float*)d_in[9];
    float*       out   = (float*)d_out;

    // one-time handles (host-side objects only; no device memory)
    static cudaStream_t s2 = nullptr, s3 = nullptr;
    static cudaEvent_t ev_fork = nullptr, ev_join = nullptr, ev_det = nullptr,
                       ev_cs = nullptr, ev_hist = nullptr, ev_dis = nullptr,
                       ev_g1 = nullptr;
    if (!s2) {
        cudaStreamCreateWithFlags(&s2, cudaStreamNonBlocking);
        cudaStreamCreateWithFlags(&s3, cudaStreamNonBlocking);
        cudaEventCreateWithFlags(&ev_fork, cudaEventDisableTiming);
        cudaEventCreateWithFlags(&ev_join, cudaEventDisableTiming);
        cudaEventCreateWithFlags(&ev_det, cudaEventDisableTiming);
        cudaEventCreateWithFlags(&ev_cs, cudaEventDisableTiming);
        cudaEventCreateWithFlags(&ev_hist, cudaEventDisableTiming);
        cudaEventCreateWithFlags(&ev_dis, cudaEventDisableTiming);
        cudaEventCreateWithFlags(&ev_g1, cudaEventDisableTiming);
        cudaFuncSetAttribute(k_gemm1t,
                             cudaFuncAttributeMaxDynamicSharedMemorySize, GSMEM);
    }

    int nw = (N_NODES * NC2 + 255) / 256;
    int fin_blocks = (N_NODES + 255) / 256;

    // ---- fork: W1 split + GEMM1 + FC2 on s2 ----
    cudaEventRecord(ev_fork, 0);
    cudaStreamWaitEvent(s2, ev_fork, 0);
    k_wsplit<<<(HID * IN_DIM + 255) / 256, 256, 0, s2>>>(w1);

    k_detect<<<1, 256>>>((const int*)ei, (const unsigned char*)mask);
    cudaEventRecord(ev_det, 0);
    k_init<<<(N_NODES + 255) / 256, 256>>>(mask);

    k_gemm1t<<<(N_NODES + GBM - 1) / GBM, 512, GSMEM, s2>>>(x, b1);
    cudaEventRecord(ev_g1, s2);
    k_fc2<<<fin_blocks, 256, 0, s2>>>(w2, b2);
    cudaEventRecord(ev_join, s2);

    // s3: convstamp (needs only detect's flags)
    cudaStreamWaitEvent(s3, ev_det, 0);
    k_convstamp<<<nw, 256, 0, s3>>>(linit, mask, hard);
    cudaEventRecord(ev_cs, s3);

    // main: hist
    k_hist<<<(E_EDGES + 255) / 256, 256>>>(ei, mask);
    cudaEventRecord(ev_hist, 0);

    // s3: dis (needs hist) concurrent with scans on main
    cudaStreamWaitEvent(s3, ev_hist, 0);
    k_dis<<<(N_NODES + 255) / 256, 256, 0, s3>>>();
    cudaEventRecord(ev_dis, s3);

    k_scan1<<<NBLK, SCAN_B>>>();
    k_scan2<<<1, 128>>>();
    k_scan3<<<NBLK, SCAN_B>>>();
    cudaStreamWaitEvent(0, ev_dis, 0);
    k_fill<<<(TOT_E + 255) / 256, 256>>>(ei, mask);

    // persistent PLP: needs fill + convstamp; waits for gemm so its
    // co-resident grid doesn't freeze gemm's full-RF waves.
    cudaStreamWaitEvent(0, ev_cs, 0);
    cudaStreamWaitEvent(0, ev_g1, 0);
    k_plp10<<<PLP_BLOCKS, 256>>>(mask, hard);

    // combine: needs g_logits (s2) and g_B0h (after plp10)
    cudaStreamWaitEvent(0, ev_join, 0);
    k_combine<<<(N_NODES * (NC / 4) + 255) / 256, 256>>>(alpha, out);
}